// round 13
// baseline (speedup 1.0000x reference)
#include <cuda_runtime.h>
#include <cuda_bf16.h>
#include <cstdint>
#include <cstddef>

// ---------------------------------------------------------------------------
// CVAE forward, Round 11: layer-wavefront. One 128-CTA launch runs layer0 and
// layer1 of a stack concurrently (64 CTAs each, flag-coupled); layer2 follows
// as a 64-CTA plain launch. mma.sync bf16, warp tile 32x32, fused next-layer
// input projection, quarter-streamed A images, dataflow flags.
// B=256 T=128 U=512 LAT=200 V=42 P=3
// ---------------------------------------------------------------------------

constexpr int cB = 256, cT = 128, cU = 512, cLAT = 200, cV = 42, cP = 3;
constexpr int G4U = 2048;
constexpr int NTHR = 256;
constexpr int SMSZ = 65536 * 3 + 4096;   // Wr 64K | Wk 64K | Abuf 64K | hbuf 4K

// ------------------------------- scratch -----------------------------------
__device__ float g_pre1[(size_t)cB * cT * G4U];   // L0 -> L1
__device__ float g_pre2[(size_t)cB * cT * G4U];   // L1 -> L2
__device__ __nv_bfloat16 g_seq[(size_t)cB * cT * cU];
__device__ uint4 g_imgA[2][cT + 1][8192];         // layer0 / layer2 h images
__device__ uint4 g_imgB[2][cT + 1][8192];         // layer1 h images
__device__ float g_c[cB * cU];
__device__ float g_Eenc[cV * G4U];
__device__ float g_Edec[cV * G4U];
__device__ float g_CbEnc[cB * G4U];
__device__ float g_CbDec[cB * G4U];
__device__ float g_Cz[cB * G4U];
__device__ float g_z[cB * cLAT];
__device__ float g_latpart[cB];
__device__ float g_reconpart[512];
__device__ unsigned g_flag[6 * 64];               // pass x sbg(2) x utile(32)

// ------------------------------ helpers ------------------------------------
__device__ __forceinline__ void cpa16(void* d, const void* s) {
    unsigned ds = (unsigned)__cvta_generic_to_shared(d);
    asm volatile("cp.async.cg.shared.global [%0], [%1], 16;" :: "r"(ds), "l"(s));
}
__device__ __forceinline__ unsigned bf2(float a, float b) {
    __nv_bfloat162 p = __floats2bfloat162_rn(a, b);
    return *(unsigned*)&p;
}
__device__ __forceinline__ void mma16(float* c, uint4 a, uint2 b) {
    asm volatile(
        "mma.sync.aligned.m16n8k16.row.col.f32.bf16.bf16.f32 "
        "{%0,%1,%2,%3},{%4,%5,%6,%7},{%8,%9},{%0,%1,%2,%3};"
        : "+f"(c[0]), "+f"(c[1]), "+f"(c[2]), "+f"(c[3])
        : "r"(a.x), "r"(a.y), "r"(a.z), "r"(a.w), "r"(b.x), "r"(b.y));
}
__device__ __forceinline__ float sigf(float x) {
    float r;
    asm("{\n\t.reg .f32 t;\n\tmul.f32 t, %1, 0fBFB8AA3B;\n\t"
        "ex2.approx.f32 t, t;\n\tadd.f32 t, t, 0f3F800000;\n\t"
        "rcp.approx.f32 %0, t;\n\t}" : "=f"(r) : "f"(x));
    return r;
}
__device__ __forceinline__ float tanha(float x) {
    float r;
    asm("tanh.approx.f32 %0, %1;" : "=f"(r) : "f"(x));
    return r;
}
__device__ __forceinline__ void waitq(const unsigned* f, unsigned tgt, int lane) {
    unsigned done;
    do {
        unsigned v = tgt;
        if (lane < 8)
            asm volatile("ld.acquire.gpu.global.u32 %0, [%1];"
                         : "=r"(v) : "l"(f + lane) : "memory");
        done = __ballot_sync(0xffffffffu, v >= tgt);
    } while (done != 0xffffffffu);
}

// ------------------------------ prep kernel --------------------------------
__global__ void prep_kernel(const float* __restrict__ emb_enc,
                            const float* __restrict__ emb_dec,
                            const float* __restrict__ enc_k0,
                            const float* __restrict__ dec_k0,
                            const float* __restrict__ enc_b0,
                            const float* __restrict__ dec_b0,
                            const float* __restrict__ Cmat) {
    const int bid = blockIdx.x, tid = threadIdx.x;
    if (bid < 84) {
        const int v = bid < 42 ? bid : bid - 42;
        const float* emb = bid < 42 ? emb_enc : emb_dec;
        const float* k0 = bid < 42 ? enc_k0 : dec_k0 + (size_t)cLAT * G4U;
        float* dst = bid < 42 ? g_Eenc : g_Edec;
        for (int n = tid; n < G4U; n += NTHR) {
            float acc = 0.f;
            for (int l = 0; l < cLAT; l++)
                acc += emb[v * cLAT + l] * k0[(size_t)l * G4U + n];
            dst[v * G4U + n] = acc;
        }
    } else if (bid < 596) {
        const int b = bid < 340 ? bid - 84 : bid - 340;
        const float* k0 = bid < 340 ? enc_k0 + (size_t)cLAT * G4U
                                    : dec_k0 + (size_t)2 * cLAT * G4U;
        const float* bb = bid < 340 ? enc_b0 : dec_b0;
        float* dst = bid < 340 ? g_CbEnc : g_CbDec;
        for (int n = tid; n < G4U; n += NTHR) {
            float acc = bb[n];
            for (int p = 0; p < cP; p++)
                acc += Cmat[b * cP + p] * k0[(size_t)p * G4U + n];
            dst[b * G4U + n] = acc;
        }
    } else if (bid < 600) {
        int i = bid - 596;
        uint4* p = (i < 2) ? &g_imgA[i][0][0] : &g_imgB[i - 2][0][0];
        for (int j = tid; j < 8192; j += NTHR) p[j] = make_uint4(0, 0, 0, 0);
    } else {
        for (int i = tid; i < 6 * 64; i += NTHR) g_flag[i] = 0u;
    }
}

// --------------------------- recurrent kernel ------------------------------
// TWO: grid 128. bid>>6 = layer (0: E-mode + fuse->pre1; 1: pre1-mode + fuse->pre2)
// !TWO: grid 64. pre2-mode, no fuse, writes g_c (+g_seq if wrseq).
// Within layer: 64 CTAs = 2 sbg(128 rows) x 32 utiles(16 units -> 64 gate cols).
template <bool TWO>
__global__ __launch_bounds__(256, 1)
void rec7_kernel(const float* __restrict__ Wr0, const float* __restrict__ Wk0,
                 const float* __restrict__ bn0,
                 const float* __restrict__ Wr1, const float* __restrict__ Wk1,
                 const float* __restrict__ bn1,
                 const int* __restrict__ Xidx, int sel_dec, int pass_base,
                 int wrseq) {
    extern __shared__ char sm[];
    unsigned* WrS = (unsigned*)sm;                     // 64KB
    unsigned* WkS = (unsigned*)(sm + 65536);           // 64KB
    uint4* Abuf = (uint4*)(sm + 131072);               // 2 x 32KB
    __nv_bfloat16* hbuf = (__nv_bfloat16*)(sm + 196608);  // 4KB

    const int tid = threadIdx.x, lane = tid & 31, w = tid >> 5;
    const int wm = w & 3, wn = w >> 2;
    int bid = blockIdx.x;
    const int layer = TWO ? (bid >> 6) : 0;
    bid &= 63;
    const int sbg = bid >> 5, utile = bid & 31;
    const int u0 = utile * 16;
    const int b0 = sbg * 128;
    const bool EMODE = TWO && (layer == 0);
    const float* Wr = layer ? Wr1 : Wr0;
    const float* Wk = layer ? Wk1 : Wk0;
    const float* bn = layer ? bn1 : bn0;
    const int pass = pass_base + (TWO ? layer : 2);
    uint4 (*img)[8192] = TWO ? (layer ? g_imgB[sbg] : g_imgA[sbg]) : g_imgA[sbg];
    const float* preS = TWO ? g_pre1 : g_pre2;
    float* preD = (TWO && layer == 0) ? g_pre1 : g_pre2;

    // ---- stage weights (R5-verified fragment layout, gate-grouped) ----
    for (int i = tid; i < 16384; i += 256) {
        int c = i & 63, kp = i >> 6, k = kp * 2;
        int grp = c >> 3, j = c & 7;
        int gcol = (grp & 3) * 512 + u0 + (grp >> 2) * 8 + j;
        int chunk = k >> 4, kk = k & 15;
        int ln = j * 4 + ((kk & 7) >> 1);
        int rg = kk >> 3;
        int off = ((grp * 32 + chunk) * 32 + ln) * 2 + rg;
        WrS[off] = bf2(Wr[(size_t)k * G4U + gcol], Wr[(size_t)(k + 1) * G4U + gcol]);
        if (TWO)
            WkS[off] = bf2(Wk[(size_t)k * G4U + gcol], Wk[(size_t)(k + 1) * G4U + gcol]);
    }

    const int r0 = wm * 32 + (lane >> 2);          // local row base (0..127)
    const int uc = u0 + wn * 8 + (lane & 3) * 2;   // global unit col base
    const unsigned* flg = &g_flag[pass * 64 + sbg * 32];
    unsigned* myflag = &g_flag[pass * 64 + sbg * 32 + utile];
    const unsigned* srcflag = &g_flag[pass_base * 64 + sbg * 32 + utile];
    const float* Etab = sel_dec ? g_Edec : g_Eenc;
    const float* Cb = sel_dec ? g_Cz : g_CbEnc;

    float2 bnv[4];
    if (TWO) {
#pragma unroll
        for (int g = 0; g < 4; g++)
            bnv[g] = *(const float2*)&bn[g * 512 + uc];
    }
    float cst[8];
#pragma unroll
    for (int j = 0; j < 8; j++) cst[j] = 0.f;

    const int TMAX = TWO ? 129 : 128;
    for (int t = 0; t < TMAX; t++) {
        const bool doR = (t < 128);
        const bool doK = TWO && (t > 0);
        const uint4* slot = img[t];

        // stage quarters 0,1 into Abuf[0],Abuf[1]
#pragma unroll
        for (int q = 0; q < 2; q++) {
            if (t > 0) waitq(flg + q * 8, (unsigned)t, lane);
#pragma unroll
            for (int j = 0; j < 8; j++) {
                int idx = tid + j * 256;
                cpa16(&Abuf[q * 2048 + idx], slot + q * 2048 + idx);
            }
            asm volatile("cp.async.commit_group;");
        }

        float accR[2][4][4], accK[2][4][4];
#pragma unroll
        for (int f = 0; f < 2; f++)
#pragma unroll
            for (int g = 0; g < 4; g++)
#pragma unroll
                for (int q = 0; q < 4; q++) { accR[f][g][q] = 0.f; accK[f][g][q] = 0.f; }

#pragma unroll
        for (int q = 0; q < 4; q++) {
            if (q < 3) asm volatile("cp.async.wait_group 1;" ::: "memory");
            else       asm volatile("cp.async.wait_group 0;" ::: "memory");
            __syncthreads();
            const uint4* Ab = &Abuf[(q & 1) * 2048];
#pragma unroll
            for (int ch = 0; ch < 8; ch++) {
                int c = q * 8 + ch;
                uint4 af0 = Ab[((2 * wm) * 8 + ch) * 32 + lane];
                uint4 af1 = Ab[((2 * wm + 1) * 8 + ch) * 32 + lane];
#pragma unroll
                for (int g = 0; g < 4; g++) {
                    uint2 bf = *(const uint2*)(WrS + (((wn * 4 + g) * 32 + c) * 32 + lane) * 2);
                    if (doR) { mma16(accR[0][g], af0, bf); mma16(accR[1][g], af1, bf); }
                    if (TWO) {
                        uint2 bk = *(const uint2*)(WkS + (((wn * 4 + g) * 32 + c) * 32 + lane) * 2);
                        mma16(accK[0][g], af0, bk); mma16(accK[1][g], af1, bk);
                    }
                }
            }
            __syncthreads();
            if (q < 2) {
                int q2 = q + 2;
                if (t > 0) waitq(flg + q2 * 8, (unsigned)t, lane);
#pragma unroll
                for (int j = 0; j < 8; j++) {
                    int idx = tid + j * 256;
                    cpa16(&Abuf[(q & 1) * 2048 + idx], slot + q2 * 2048 + idx);
                }
                asm volatile("cp.async.commit_group;");
            }
        }

        // ---- fused pre write: accK = h(t-1)@Wk -> pre(t-1) ----
        if (doK) {
#pragma unroll
            for (int f = 0; f < 2; f++) {
                int row = r0 + 16 * f;
#pragma unroll
                for (int g = 0; g < 4; g++) {
                    size_t o1 = ((size_t)(b0 + row) * cT + (t - 1)) * G4U + g * 512 + uc;
                    size_t o2 = ((size_t)(b0 + row + 8) * cT + (t - 1)) * G4U + g * 512 + uc;
                    __stcs((float2*)&preD[o1],
                           make_float2(accK[f][g][0] + bnv[g].x, accK[f][g][1] + bnv[g].y));
                    __stcs((float2*)&preD[o2],
                           make_float2(accK[f][g][2] + bnv[g].x, accK[f][g][3] + bnv[g].y));
                }
            }
        }

        // ---- recurrence epilogue ----
        if (doR) {
            if (TWO && layer == 1) {
                unsigned v;
                do {
                    asm volatile("ld.acquire.gpu.global.u32 %0, [%1];"
                                 : "=r"(v) : "l"(srcflag) : "memory");
                } while (v < (unsigned)(t + 2));
            }
            float2 za[4][4];
#pragma unroll
            for (int ri = 0; ri < 4; ri++) {
                int b = b0 + r0 + 8 * ri;
                if (EMODE) {
                    int xi = Xidx[b * cT + t];
#pragma unroll
                    for (int g = 0; g < 4; g++) {
                        float2 e = *(const float2*)&Etab[xi * G4U + g * 512 + uc];
                        float2 cc = *(const float2*)&Cb[(size_t)b * G4U + g * 512 + uc];
                        za[ri][g] = make_float2(e.x + cc.x, e.y + cc.y);
                    }
                } else {
#pragma unroll
                    for (int g = 0; g < 4; g++)
                        za[ri][g] = __ldcs((const float2*)&preS[
                            ((size_t)b * cT + t) * G4U + g * 512 + uc]);
                }
            }
#pragma unroll
            for (int ri = 0; ri < 4; ri++) {
                const int f = ri >> 1, hi = (ri & 1) * 2;
                const int row = r0 + 8 * ri;
                float h2v[2];
#pragma unroll
                for (int pq = 0; pq < 2; pq++) {
                    const int ci = ri * 2 + pq;
                    float zi = accR[f][0][hi + pq] + (pq ? za[ri][0].y : za[ri][0].x);
                    float zf = accR[f][1][hi + pq] + (pq ? za[ri][1].y : za[ri][1].x);
                    float zg = accR[f][2][hi + pq] + (pq ? za[ri][2].y : za[ri][2].x);
                    float zo = accR[f][3][hi + pq] + (pq ? za[ri][3].y : za[ri][3].x);
                    float ig = sigf(zi), fg = sigf(zf), gv = tanhf(zg), og = sigf(zo);
                    cst[ci] = fg * cst[ci] + ig * gv;
                    float h2 = og * tanha(cst[ci]);
                    h2v[pq] = h2;
                    const int ul = wn * 8 + (lane & 3) * 2 + pq;
                    const int strip = row >> 4, rr2 = row & 15;
                    const int ln2 = (rr2 & 7) * 4 + ((ul & 7) >> 1);
                    const int rg = (rr2 >> 3) + 2 * (ul >> 3);
                    hbuf[strip * 256 + ln2 * 8 + rg * 2 + (ul & 1)] = __float2bfloat16(h2);
                }
                if (wrseq)
                    *(unsigned*)&g_seq[((size_t)(b0 + row) * cT + t) * cU + uc] =
                        bf2(h2v[0], h2v[1]);
            }
            __syncthreads();
            {   // coalesced publish: 256 x uint4 into slot t+1
                int strip = tid >> 5, l2 = tid & 31;
                uint4 v = ((const uint4*)hbuf)[strip * 32 + l2];
                img[t + 1][(((utile >> 3) * 8 + strip) * 8 + (utile & 7)) * 32 + l2] = v;
            }
            __syncthreads();
            if (tid == 0)
                asm volatile("red.release.gpu.global.add.u32 [%0], 1;"
                             :: "l"(myflag) : "memory");
        } else {
            __syncthreads();
            if (tid == 0)
                asm volatile("red.release.gpu.global.add.u32 [%0], 1;"
                             :: "l"(myflag) : "memory");
        }
    }

    if (!TWO) {
#pragma unroll
        for (int ri = 0; ri < 4; ri++) {
            int row = r0 + 8 * ri;
            *(float2*)&g_c[(size_t)(b0 + row) * cU + uc] =
                make_float2(cst[ri * 2], cst[ri * 2 + 1]);
        }
    }
}

// ----------------------- latent / zproj / ce / finish ----------------------
__global__ void latz_kernel(const float* __restrict__ Wm, const float* __restrict__ bm,
                            const float* __restrict__ Ws, const float* __restrict__ bs,
                            const float* __restrict__ eps) {
    __shared__ float csh[cU];
    __shared__ float red[NTHR];
    const int b = blockIdx.x, tid = threadIdx.x;
    csh[tid] = g_c[b * cU + tid];
    csh[tid + 256] = g_c[b * cU + tid + 256];
    __syncthreads();
    float term = 0.f;
    if (tid < cLAT) {
        float m = bm[tid], ls = bs[tid];
        for (int u = 0; u < cU; u++) {
            const float cv = csh[u];
            m += cv * Wm[u * cLAT + tid];
            ls += cv * Ws[u * cLAT + tid];
        }
        g_z[b * cLAT + tid] = m + expf(0.5f * ls) * eps[b * cLAT + tid];
        term = 1.f + ls - m * m - expf(ls);
    }
    red[tid] = term;
    __syncthreads();
    for (int s = 128; s > 0; s >>= 1) {
        if (tid < s) red[tid] += red[tid + s];
        __syncthreads();
    }
    if (tid == 0) g_latpart[b] = red[0];
}

__global__ void zproj_kernel(const float* __restrict__ dec_k0) {
    __shared__ float zsh[cLAT];
    const int b = blockIdx.x, tid = threadIdx.x;
    if (tid < cLAT) zsh[tid] = g_z[b * cLAT + tid];
    __syncthreads();
    for (int n = tid; n < G4U; n += NTHR) {
        float acc = g_CbDec[b * G4U + n];
        for (int l = 0; l < cLAT; l++) acc += zsh[l] * dec_k0[(size_t)l * G4U + n];
        g_Cz[b * G4U + n] = acc;
    }
}

__global__ void ce_kernel(const float* __restrict__ Wo, const float* __restrict__ bo,
                          const int* __restrict__ Y, const int* __restrict__ Lv) {
    __shared__ float hsh[8][cU];
    __shared__ float wred[8];
    const int tid = threadIdx.x, w = tid >> 5, lane = tid & 31;
    const int gw = blockIdx.x * 8 + w;
    float sum = 0.f;
    for (int j = 0; j < 8; j++) {
        const int idx = gw + j * 4096;
        const int b = idx >> 7, t = idx & 127;
        const __nv_bfloat16* hp = &g_seq[((size_t)b * cT + t) * cU];
        for (int i = lane; i < cU; i += 32) hsh[w][i] = __bfloat162float(hp[i]);
        __syncwarp();
        const int v0 = lane, v1 = 32 + lane;
        const int v1c = (v1 < cV) ? v1 : 0;
        float l0 = bo[v0], l1 = bo[v1c];
        for (int u = 0; u < cU; u++) {
            const float hv = hsh[w][u];
            l0 += hv * Wo[u * cV + v0];
            l1 += hv * Wo[u * cV + v1c];
        }
        if (v1 >= cV) l1 = -1e30f;
        float mx = fmaxf(l0, l1);
        for (int o = 16; o; o >>= 1) mx = fmaxf(mx, __shfl_xor_sync(~0u, mx, o));
        float s = expf(l0 - mx) + ((v1 < cV) ? expf(l1 - mx) : 0.f);
        for (int o = 16; o; o >>= 1) s += __shfl_xor_sync(~0u, s, o);
        const float lse = mx + logf(s);
        const int y = Y[b * cT + t];
        const float ly = __shfl_sync(~0u, (y < 32) ? l0 : l1, y & 31);
        if (lane == 0 && t < Lv[b]) sum += (lse - ly);
        __syncwarp();
    }
    if (lane == 0) wred[w] = sum;
    __syncthreads();
    if (tid == 0) {
        float s = 0.f;
        for (int i = 0; i < 8; i++) s += wred[i];
        g_reconpart[blockIdx.x] = s;
    }
}

__global__ void finish_kernel(float* __restrict__ out, int out_size) {
    __shared__ float red[NTHR];
    const int tid = threadIdx.x;
    float s = 0.f;
    for (int i = tid; i < 512; i += NTHR) s += g_reconpart[i];
    red[tid] = s;
    __syncthreads();
    for (int st = 128; st > 0; st >>= 1) {
        if (tid < st) red[tid] += red[tid + st];
        __syncthreads();
    }
    const float rsum = red[0];
    __syncthreads();
    float s2 = 0.f;
    for (int i = tid; i < cB; i += NTHR) s2 += g_latpart[i];
    red[tid] = s2;
    __syncthreads();
    for (int st = 128; st > 0; st >>= 1) {
        if (tid < st) red[tid] += red[tid + st];
        __syncthreads();
    }
    if (tid == 0) {
        const float recon = rsum / (float)(cB * cT);
        const float lat = -0.5f * red[0] / (float)(cB * cLAT);
        out[0] = recon + lat;
        if (out_size > 1) out[1] = recon;
        if (out_size > 2) out[2] = lat;
    }
}

// --------------------------------- launch ----------------------------------
extern "C" void kernel_launch(void* const* d_in, const int* in_sizes, int n_in,
                              void* d_out, int out_size) {
    const int* X = (const int*)d_in[0];
    const int* Y = (const int*)d_in[1];
    const float* C = (const float*)d_in[2];
    const int* L = (const int*)d_in[3];
    const float* eps = (const float*)d_in[4];
    const float* emb_enc = (const float*)d_in[5];
    const float* emb_dec = (const float*)d_in[6];
    const float* enc_k0 = (const float*)d_in[7];
    const float* enc_rk0 = (const float*)d_in[8];
    const float* enc_b0 = (const float*)d_in[9];
    const float* enc_k1 = (const float*)d_in[10];
    const float* enc_rk1 = (const float*)d_in[11];
    const float* enc_b1 = (const float*)d_in[12];
    const float* enc_k2 = (const float*)d_in[13];
    const float* enc_rk2 = (const float*)d_in[14];
    const float* enc_b2 = (const float*)d_in[15];
    const float* dec_k0 = (const float*)d_in[16];
    const float* dec_rk0 = (const float*)d_in[17];
    const float* dec_b0 = (const float*)d_in[18];
    const float* dec_k1 = (const float*)d_in[19];
    const float* dec_rk1 = (const float*)d_in[20];
    const float* dec_b1 = (const float*)d_in[21];
    const float* dec_k2 = (const float*)d_in[22];
    const float* dec_rk2 = (const float*)d_in[23];
    const float* dec_b2 = (const float*)d_in[24];
    const float* Wm = (const float*)d_in[25];
    const float* bm = (const float*)d_in[26];
    const float* Ws = (const float*)d_in[27];
    const float* bs = (const float*)d_in[28];
    const float* Wo = (const float*)d_in[29];
    const float* bo = (const float*)d_in[30];

    cudaFuncSetAttribute((const void*)rec7_kernel<true>,
                         cudaFuncAttributeMaxDynamicSharedMemorySize, SMSZ);
    cudaFuncSetAttribute((const void*)rec7_kernel<false>,
                         cudaFuncAttributeMaxDynamicSharedMemorySize, SMSZ);

    prep_kernel<<<601, NTHR>>>(emb_enc, emb_dec, enc_k0, dec_k0, enc_b0, dec_b0, C);

    // ---- encoder: L0+L1 wavefront, then L2 ----
    rec7_kernel<true><<<128, NTHR, SMSZ>>>(enc_rk0, enc_k1, enc_b1,
                                           enc_rk1, enc_k2, enc_b2, X, 0, 0, 0);
    rec7_kernel<false><<<64, NTHR, SMSZ>>>(enc_rk2, nullptr, nullptr,
                                           nullptr, nullptr, nullptr, nullptr, 0, 0, 0);

    // ---- latent ----
    latz_kernel<<<cB, NTHR>>>(Wm, bm, Ws, bs, eps);
    zproj_kernel<<<cB, NTHR>>>(dec_k0);

    // ---- decoder: L0+L1 wavefront, then L2 (writes g_seq) ----
    rec7_kernel<true><<<128, NTHR, SMSZ>>>(dec_rk0, dec_k1, dec_b1,
                                           dec_rk1, dec_k2, dec_b2, X, 1, 3, 0);
    rec7_kernel<false><<<64, NTHR, SMSZ>>>(dec_rk2, nullptr, nullptr,
                                           nullptr, nullptr, nullptr, nullptr, 1, 3, 1);

    // ---- losses ----
    ce_kernel<<<512, NTHR>>>(Wo, bo, Y, L);
    finish_kernel<<<1, NTHR>>>((float*)d_out, out_size);
}